// round 9
// baseline (speedup 1.0000x reference)
#include <cuda_runtime.h>
#include <math.h>

// Shapes fixed by the reference:
//   pred:              [N, 6]
//   dropout_preds:     [K, M, 6]
//   dropout_cls_confs: [K, M, C]
//   out:               [N]
#define N_PRED 1000
#define M_BOX  2000
#define K_PASS 10
#define C_CLS  80
#define EPS_F  1e-7f
#define CAP    32
#define INF_I  0x7fffffff

// Max |jittered copy - source pred|_inf over all K*N copies (float bits).
// atomicMax only ever raises it to the same data-determined value -> replay-safe.
__device__ unsigned g_dev = 0;

__global__ void prep_kernel(const float* __restrict__ pred,
                            const float* __restrict__ dp)
{
    const int i = blockIdx.x * blockDim.x + threadIdx.x;   // over K*N copies
    float dev = 0.0f;
    if (i < K_PASS * N_PRED) {
        const int kk = i / N_PRED;
        const int mm = i - kk * N_PRED;
        const float* b = dp + ((size_t)kk * M_BOX + mm) * 6;
        const float* p = pred + (size_t)mm * 6;
        dev = fmaxf(fmaxf(fabsf(b[0] - p[0]), fabsf(b[1] - p[1])),
                    fmaxf(fabsf(b[2] - p[2]), fabsf(b[3] - p[3])));
    }
    __shared__ unsigned s_w[8];
    const unsigned wmax = __reduce_max_sync(0xffffffffu, __float_as_uint(dev));
    if ((threadIdx.x & 31) == 0) s_w[threadIdx.x >> 5] = wmax;
    __syncthreads();
    if (threadIdx.x == 0) {
        unsigned m = 0;
        #pragma unroll
        for (int w = 0; w < (int)(blockDim.x >> 5); w++) m = max(m, s_w[w]);
        atomicMax(&g_dev, m);
    }
}

// Exact: IoU > 0.5  <=>  3*inter > (area1+eps) + area2   (s1 = area1+eps)
__device__ __forceinline__ bool hit_box(const float* __restrict__ b,
                                        float ax1, float ay1, float ax2, float ay2,
                                        float s1)
{
    const float2 b01 = *reinterpret_cast<const float2*>(b);
    const float2 b23 = *reinterpret_cast<const float2*>(b + 2);
    const float w = fminf(ax2, b23.x) - fmaxf(ax1, b01.x);
    const float h = fminf(ay2, b23.y) - fmaxf(ay1, b01.y);
    const float inter = fmaxf(w, 0.0f) * fmaxf(h, 0.0f);
    const float area2 = (b23.x - b01.x) * (b23.y - b01.y);
    return fmaf(3.0f, inter, -area2) > s1;
}

// Exact chunked early-exit scan of dp rows [start, M_BOX); first match or -1.
__device__ __forceinline__ int scan_range(const float* __restrict__ dpk, int start,
                                          float ax1, float ay1, float ax2, float ay2,
                                          float s1, int lane)
{
    for (int base = start; base < M_BOX; base += 128) {
        int l2 = INF_I;
        #pragma unroll
        for (int j = 3; j >= 0; j--) {
            const int m = base + j * 32 + lane;
            if (m < M_BOX && hit_box(dpk + (size_t)m * 6, ax1, ay1, ax2, ay2, s1))
                l2 = j * 32 + lane;
        }
        const int r = __reduce_min_sync(0xffffffffu, l2);
        if (r != INF_I) return base + r;
    }
    return -1;
}

// Exact first match for one pred: candidate copies first, then random region.
__device__ __forceinline__ int match_one(const float* __restrict__ dpk,
                                         const int* __restrict__ cand, int cnt,
                                         float ax1, float ay1, float ax2, float ay2,
                                         float s1, int lane)
{
    if (cnt <= CAP) {
        int loc = INF_I;
        for (int c = lane; c < cnt; c += 32) {
            const int m = cand[c];
            if (hit_box(dpk + (size_t)m * 6, ax1, ay1, ax2, ay2, s1))
                loc = min(loc, m);
        }
        const int r = __reduce_min_sync(0xffffffffu, loc);
        if (r != INF_I) return r;                       // min copy idx == first match
        return scan_range(dpk, N_PRED, ax1, ay1, ax2, ay2, s1, lane);
    }
    return scan_range(dpk, 0, ax1, ay1, ax2, ay2, s1, lane);  // overflow fallback
}

// Warp-cooperative: u = 1 + sum(p log p)/log(C) over a row held in q0,q1,q2.
__device__ __forceinline__ float entropy_u(float q0, float q1, float q2)
{
    float s = q0 * __logf(q0) + q1 * __logf(q1) + q2 * __logf(q2);
    #pragma unroll
    for (int off = 16; off; off >>= 1)
        s += __shfl_xor_sync(0xffffffffu, s, off);
    return 1.0f + s * (1.0f / logf((float)C_CLS));
}

// TWO preds per block (grid = 500 <= 888 concurrent -> exactly ONE wave).
// One warp per pass k, handling pass k for both preds (2x ILP per warp).
// Phase 0: speculative conf prefetch for both (m_match == n almost always).
// Phase 1: sound-bound screen over all preds, shared B-box loads, 2 tests.
// Phase 2: exact candidate tests; min hit index == first match.
__global__ __launch_bounds__(K_PASS * 32)
void ue_cls_kernel(const float* __restrict__ pred,
                   const float* __restrict__ dp,
                   const float* __restrict__ conf,
                   float* __restrict__ out)
{
    const int tid  = threadIdx.x;
    const int k    = tid >> 5;
    const int lane = tid & 31;
    const int n0   = blockIdx.x * 2;
    const int n1   = n0 + 1;

    __shared__ int   s_cand[2][CAP];
    __shared__ int   s_cnt[2];
    __shared__ float s_u[2][K_PASS];
    __shared__ int   s_m[2][K_PASS];

    // ---- Phase 0: speculative conf prefetch for BOTH preds (max front MLP) ----
    const float* __restrict__ rs0 = conf + ((size_t)k * M_BOX + n0) * C_CLS;
    const float* __restrict__ rs1 = rs0 + C_CLS;
    float q00 = rs0[lane], q01 = rs0[lane + 32];
    float q10 = rs1[lane], q11 = rs1[lane + 32];
    float q02 = (lane < C_CLS - 64) ? rs0[lane + 64] : 1.0f;  // log(1)=0 no-op
    float q12 = (lane < C_CLS - 64) ? rs1[lane + 64] : 1.0f;

    // Pred boxes
    const float2 a01 = *reinterpret_cast<const float2*>(pred + (size_t)n0 * 6);
    const float2 a23 = *reinterpret_cast<const float2*>(pred + (size_t)n0 * 6 + 2);
    const float2 c01 = *reinterpret_cast<const float2*>(pred + (size_t)n1 * 6);
    const float2 c23 = *reinterpret_cast<const float2*>(pred + (size_t)n1 * 6 + 2);
    const float a1A = (a23.x - a01.x) * (a23.y - a01.y), s1A = a1A + EPS_F;
    const float a1C = (c23.x - c01.x) * (c23.y - c01.y), s1C = a1C + EPS_F;
    const float Dv = __uint_as_float(g_dev) * 1.01f + 0.5f;   // inflated: sound

    if (tid < 2) s_cnt[tid] = 0;
    __syncthreads();

    // ---- Phase 1: sound screen, one B-box load serves both preds ----
    for (int n2 = tid; n2 < N_PRED; n2 += K_PASS * 32) {
        const float2 b01 = *reinterpret_cast<const float2*>(pred + (size_t)n2 * 6);
        const float2 b23 = *reinterpret_cast<const float2*>(pred + (size_t)n2 * 6 + 2);
        const float bx1 = b01.x - Dv, by1 = b01.y - Dv;
        const float bx2 = b23.x + Dv, by2 = b23.y + Dv;
        const float a2_lb = fmaxf(b23.x - b01.x - 2.0f * Dv, 0.0f) *
                            fmaxf(b23.y - b01.y - 2.0f * Dv, 0.0f);
        {
            const float w = fminf(a23.x, bx2) - fmaxf(a01.x, bx1);
            const float h = fminf(a23.y, by2) - fmaxf(a01.y, by1);
            if (3.0f * (fmaxf(w, 0.f) * fmaxf(h, 0.f)) > a1A + a2_lb) {
                const int pos = atomicAdd(&s_cnt[0], 1);
                if (pos < CAP) s_cand[0][pos] = n2;
            }
        }
        {
            const float w = fminf(c23.x, bx2) - fmaxf(c01.x, bx1);
            const float h = fminf(c23.y, by2) - fmaxf(c01.y, by1);
            if (3.0f * (fmaxf(w, 0.f) * fmaxf(h, 0.f)) > a1C + a2_lb) {
                const int pos = atomicAdd(&s_cnt[1], 1);
                if (pos < CAP) s_cand[1][pos] = n2;
            }
        }
    }
    __syncthreads();

    const float* __restrict__ dpk = dp + (size_t)k * M_BOX * 6;

    // ---- Phase 2: exact first-match + entropy, pred 0 then pred 1 ----
    const int m0 = match_one(dpk, s_cand[0], s_cnt[0],
                             a01.x, a01.y, a23.x, a23.y, s1A, lane);
    const int m1 = match_one(dpk, s_cand[1], s_cnt[1],
                             c01.x, c01.y, c23.x, c23.y, s1C, lane);
    if (lane == 0) { s_m[0][k] = m0; s_m[1][k] = m1; }

    if (m0 >= 0) {
        if (m0 != n0) {       // rare mispredict: reload true row
            const float* row = conf + ((size_t)k * M_BOX + (size_t)m0) * C_CLS;
            q00 = row[lane]; q01 = row[lane + 32];
            q02 = (lane < C_CLS - 64) ? row[lane + 64] : 1.0f;
        }
        const float u = entropy_u(q00, q01, q02);
        if (lane == 0) s_u[0][k] = u;
    }
    if (m1 >= 0) {
        if (m1 != n1) {
            const float* row = conf + ((size_t)k * M_BOX + (size_t)m1) * C_CLS;
            q10 = row[lane]; q11 = row[lane + 32];
            q12 = (lane < C_CLS - 64) ? row[lane + 64] : 1.0f;
        }
        const float u = entropy_u(q10, q11, q12);
        if (lane == 0) s_u[1][k] = u;
    }

    __syncthreads();

    if (tid < 2) {
        float sum = 0.0f;
        int   cc = 0;
        #pragma unroll
        for (int kk = 0; kk < K_PASS; kk++) {
            if (s_m[tid][kk] >= 0) { sum += s_u[tid][kk]; cc++; }
        }
        out[n0 + tid] = (cc > 0) ? (sum / (float)cc) : __int_as_float(0x7fc00000);
    }
}

extern "C" void kernel_launch(void* const* d_in, const int* in_sizes, int n_in,
                              void* d_out, int out_size)
{
    const float* pred = (const float*)d_in[0];
    const float* dp   = (const float*)d_in[1];
    const float* conf = (const float*)d_in[2];
    float* out = (float*)d_out;

    prep_kernel<<<(K_PASS * N_PRED + 255) / 256, 256>>>(pred, dp);
    ue_cls_kernel<<<N_PRED / 2, K_PASS * 32>>>(pred, dp, conf, out);
}